// round 15
// baseline (speedup 1.0000x reference)
#include <cuda_runtime.h>

#define H 8192
#define W 8192
#define KH 7
#define KW 7
#define OH (H - KH + 1)   // 8186
#define OW (W - KW + 1)   // 8186

#define TPB    256         // 8 warps
#define RPT    16          // rows per thread
#define TILE_X 64          // 32 lanes * 2 cols (one f32x2 pair)
#define TILE_Y 128         // 8 warps * 16 rows
#define SM_H   (TILE_Y + KH - 1)   // 134
#define SM_W   (TILE_X + KW - 1)   // 70
#define SP     72                  // smem row pitch (floats)
#define VLEN   (RPT + KH - 1)      // 22

typedef unsigned long long u64;

__device__ __forceinline__ u64 fma2(u64 a, u64 b, u64 c) {
    u64 d;
    asm("fma.rn.f32x2 %0, %1, %2, %3;" : "=l"(d) : "l"(a), "l"(b), "l"(c));
    return d;
}
__device__ __forceinline__ u64 splat2(float w) {
    u64 d;
    asm("mov.b64 %0, {%1, %1};" : "=l"(d) : "f"(w));
    return d;
}
// pack two scalars into a u64 pair (register-pair naming, ~free)
__device__ __forceinline__ u64 pack2(float lo, float hi) {
    u64 d;
    asm("mov.b64 %0, {%1, %2};" : "=l"(d) : "f"(lo), "f"(hi));
    return d;
}

__global__ __launch_bounds__(TPB)
void conv7x7_sc_kernel(const float* __restrict__ x,
                       const float* __restrict__ wgt,
                       const float* __restrict__ bias,
                       float* __restrict__ out)
{
    __shared__ __align__(16) float smA[SM_H * SP];     // single tile copy
    __shared__ __align__(16) u64 wpair[KW * KH];       // [kc*7+kr] = {w,w}

    const int tid  = threadIdx.x;
    const int col0 = blockIdx.x * TILE_X;
    const int row0 = blockIdx.y * TILE_Y;

    if (tid < KH * KW) {
        const int kc = tid / 7;
        const int kr = tid - kc * 7;
        wpair[tid] = splat2(wgt[kr * KW + kc]);
    }

    // ---- Tile fill: clamped reads, division-free main region ----
    // Main: cols 0..63. 256 threads = 64 cols x 4 row phases; 134 rows.
    {
        const int c   = tid & 63;
        const int rph = tid >> 6;          // 0..3
        const int gc  = min(col0 + c, W - 1);
#pragma unroll 2
        for (int r = rph; r < SM_H; r += 4) {
            const int gr = min(row0 + r, H - 1);
            smA[r * SP + c] = __ldg(&x[(size_t)gr * W + gc]);
        }
    }
    // Halo: cols 64..69, 134 rows x 6 cols = 804 elems.
#pragma unroll
    for (int k = 0; k < 4; k++) {
        const int idx = tid + k * TPB;     // 0..1023
        if (idx < SM_H * 6) {
            const int r = idx / 6;
            const int c = 64 + (idx - r * 6);
            const int gr = min(row0 + r, H - 1);
            const int gc = min(col0 + c, W - 1);
            smA[r * SP + c] = __ldg(&x[(size_t)gr * W + gc]);
        }
    }
    __syncthreads();

    // ---- Compute: 2 cols x 16 rows per thread; batch loads per kc step ----
    const int lane  = tid & 31;
    const int rbase = (tid >> 5) * RPT;    // 0,16,...,112
    const int cb    = lane * 2;            // 0..62

    u64 acc[RPT];
#pragma unroll
    for (int o = 0; o < RPT; o++) acc[o] = 0ULL;

    const float* base = &smA[rbase * SP + cb];

#pragma unroll
    for (int kc = 0; kc < KW; kc++) {
        u64 w2[KH];
#pragma unroll
        for (int kr = 0; kr < KH; kr++) w2[kr] = wpair[kc * 7 + kr];

        u64 v[VLEN];
        if ((kc & 1) == 0) {
#pragma unroll
            for (int t = 0; t < VLEN; t++)
                v[t] = *(const u64*)(base + t * SP + kc);       // aligned LDS.64
        } else {
#pragma unroll
            for (int t = 0; t < VLEN; t++) {
                const float* p = base + t * SP + kc;
                v[t] = pack2(p[0], p[1]);                        // 2x LDS.32, same bytes
            }
        }

#pragma unroll
        for (int kr = 0; kr < KH; kr++)
#pragma unroll
            for (int o = 0; o < RPT; o++)
                acc[o] = fma2(v[kr + o], w2[kr], acc[o]);
    }

    // ---- Epilogue: bias + STG.64 (OW even: pairs never straddle) ----
    const u64 b2 = splat2(__ldg(&bias[0]));
    const int ocol = col0 + cb;
    if (ocol < OW) {
#pragma unroll
        for (int o = 0; o < RPT; o++) {
            const int orow = row0 + rbase + o;
            if (orow < OH) {
                u64 r;
                asm("add.rn.f32x2 %0, %1, %2;" : "=l"(r) : "l"(acc[o]), "l"(b2));
                *(u64*)&out[(size_t)orow * OW + ocol] = r;
            }
        }
    }
}

extern "C" void kernel_launch(void* const* d_in, const int* in_sizes, int n_in,
                              void* d_out, int out_size)
{
    const float* x    = (const float*)d_in[0];
    const float* wgt  = (const float*)d_in[1];
    const float* bias = (const float*)d_in[2];
    float* out        = (float*)d_out;

    dim3 block(TPB, 1, 1);
    dim3 grid((OW + TILE_X - 1) / TILE_X, (OH + TILE_Y - 1) / TILE_Y, 1);
    conv7x7_sc_kernel<<<grid, block>>>(x, wgt, bias, out);
}

// round 16
// speedup vs baseline: 1.2979x; 1.2979x over previous
#include <cuda_runtime.h>

#define H 8192
#define W 8192
#define KH 7
#define KW 7
#define OH (H - KH + 1)   // 8186
#define OW (W - KW + 1)   // 8186

#define TILE_X 64          // 32 lanes * 2 cols (one f32x2 pair)
#define TILE_Y 128         // 8 warps * 16 rows
#define TPB   256
#define RPT   16           // rows per thread (R3-proven shape)
#define SM_H  (TILE_Y + KH - 1)   // 134
#define SM_W  (TILE_X + KW - 1)   // 70
#define SP    72                  // smem row pitch (floats)
#define VLEN  (RPT + KH - 1)      // 22

typedef unsigned long long u64;

__device__ __forceinline__ u64 fma2(u64 a, u64 b, u64 c) {
    u64 d;
    asm("fma.rn.f32x2 %0, %1, %2, %3;" : "=l"(d) : "l"(a), "l"(b), "l"(c));
    return d;
}
__device__ __forceinline__ u64 splat2(float w) {
    u64 d;
    asm("mov.b64 %0, {%1, %1};" : "=l"(d) : "f"(w));
    return d;
}

__global__ __launch_bounds__(TPB)
void conv7x7_r16b_kernel(const float* __restrict__ x,
                         const float* __restrict__ wgt,
                         const float* __restrict__ bias,
                         float* __restrict__ out)
{
    __shared__ __align__(16) float smA[SM_H * SP];   // tile
    __shared__ __align__(16) float smB[SM_H * SP];   // tile shifted left 1 col
    __shared__ float wsm[KH * KW];

    const int tid  = threadIdx.x;
    const int col0 = blockIdx.x * TILE_X;
    const int row0 = blockIdx.y * TILE_Y;

    if (tid < KH * KW) wsm[tid] = wgt[tid];

    // ---- Tile fill (R3-proven fused dual-copy): clamped, division-free ----
    // Main: cols 0..63. 256 threads = 64 cols x 4 row phases; 134 rows.
    {
        const int c   = tid & 63;
        const int rph = tid >> 6;          // 0..3
        const int gc  = min(col0 + c, W - 1);
#pragma unroll 2
        for (int r = rph; r < SM_H; r += 4) {
            const int gr = min(row0 + r, H - 1);
            const float v = __ldg(&x[(size_t)gr * W + gc]);
            smA[r * SP + c] = v;
            if (c > 0) smB[r * SP + c - 1] = v;
        }
    }
    // Halo: cols 64..69, 134 rows x 6 cols = 804 elems.
#pragma unroll
    for (int k = 0; k < 4; k++) {
        const int idx = tid + k * TPB;     // 0..1023
        if (idx < SM_H * 6) {
            const int r = idx / 6;
            const int c = 64 + (idx - r * 6);
            const int gr = min(row0 + r, H - 1);
            const int gc = min(col0 + c, W - 1);
            const float v = __ldg(&x[(size_t)gr * W + gc]);
            smA[r * SP + c] = v;
            smB[r * SP + c - 1] = v;       // 63..68
        }
    }
    __syncthreads();

    // ---- Compute: 2 cols x 16 rows per thread, batch loads per kc step ----
    const int lane  = tid & 31;
    const int rbase = (tid >> 5) * RPT;    // 0,16,...,112
    const int cb    = lane * 2;            // 0..62

    u64 acc[RPT];
#pragma unroll
    for (int o = 0; o < RPT; o++) acc[o] = 0ULL;

    const float* baseA = &smA[rbase * SP + cb];
    const float* baseB = &smB[rbase * SP + cb];

#pragma unroll
    for (int kc = 0; kc < KW; kc++) {
        const float* p = (kc & 1) ? (baseB + (kc - 1)) : (baseA + kc);

        u64 w2[KH];
#pragma unroll
        for (int kr = 0; kr < KH; kr++) w2[kr] = splat2(wsm[kr * KW + kc]);

        u64 v[VLEN];
#pragma unroll
        for (int t = 0; t < VLEN; t++)
            v[t] = *(const u64*)(p + t * SP);          // aligned LDS.64, batched

#pragma unroll
        for (int kr = 0; kr < KH; kr++)
#pragma unroll
            for (int o = 0; o < RPT; o++)
                acc[o] = fma2(v[kr + o], w2[kr], acc[o]);
    }

    // ---- Epilogue: bias add + STG.64 (OW even: pairs never straddle) ----
    const u64 b2 = splat2(__ldg(&bias[0]));
    const int ocol = col0 + cb;
    if (ocol < OW) {
#pragma unroll
        for (int o = 0; o < RPT; o++) {
            const int orow = row0 + rbase + o;
            if (orow < OH) {
                u64 r;
                asm("add.rn.f32x2 %0, %1, %2;" : "=l"(r) : "l"(acc[o]), "l"(b2));
                *(u64*)&out[(size_t)orow * OW + ocol] = r;
            }
        }
    }
}

extern "C" void kernel_launch(void* const* d_in, const int* in_sizes, int n_in,
                              void* d_out, int out_size)
{
    const float* x    = (const float*)d_in[0];
    const float* wgt  = (const float*)d_in[1];
    const float* bias = (const float*)d_in[2];
    float* out        = (float*)d_out;

    dim3 block(TPB, 1, 1);
    dim3 grid((OW + TILE_X - 1) / TILE_X, (OH + TILE_Y - 1) / TILE_Y, 1);
    conv7x7_r16b_kernel<<<grid, block>>>(x, wgt, bias, out);
}

// round 17
// speedup vs baseline: 3.4959x; 2.6935x over previous
#include <cuda_runtime.h>

#define H 8192
#define W 8192
#define KH 7
#define KW 7
#define OH (H - KH + 1)   // 8186
#define OW (W - KW + 1)   // 8186

#define TILE_X 64          // 32 lanes * 2 cols (one f32x2 pair)
#define TILE_Y 64          // 4 warps * 16 rows
#define TPB   128
#define RPT   16           // rows per thread
#define SM_H  (TILE_Y + KH - 1)   // 70
#define SM_W  (TILE_X + KW - 1)   // 70
#define SP    72                  // smem row pitch (floats)
#define VLEN  (RPT + KH - 1)      // 22

typedef unsigned long long u64;

__device__ __forceinline__ u64 fma2(u64 a, u64 b, u64 c) {
    u64 d;
    asm("fma.rn.f32x2 %0, %1, %2, %3;" : "=l"(d) : "l"(a), "l"(b), "l"(c));
    return d;
}
__device__ __forceinline__ u64 splat2(float w) {
    u64 d;
    asm("mov.b64 %0, {%1, %1};" : "=l"(d) : "f"(w));
    return d;
}

__global__ __launch_bounds__(TPB, 4)
void conv7x7_r16_kernel(const float* __restrict__ x,
                        const float* __restrict__ wgt,
                        const float* __restrict__ bias,
                        float* __restrict__ out)
{
    __shared__ __align__(16) float smA[SM_H * SP];   // tile
    __shared__ __align__(16) float smB[SM_H * SP];   // tile shifted left 1 col
    __shared__ float wsm[KH * KW];

    const int tid  = threadIdx.x;
    const int col0 = blockIdx.x * TILE_X;
    const int row0 = blockIdx.y * TILE_Y;

    if (tid < KH * KW) wsm[tid] = wgt[tid];

    // ---- Tile fill: clamped reads, division-free main region ----
    // Main: cols 0..63, 128 threads = 64 cols x 2 row phases, 35 row-steps.
    {
        const int c   = tid & 63;
        const int rph = tid >> 6;
        const int gc  = min(col0 + c, W - 1);
#pragma unroll
        for (int r = 0; r < SM_H; r += 2) {
            const int rr = r + rph;                    // 0..69
            const int gr = min(row0 + rr, H - 1);
            const float v = __ldg(&x[gr * W + gc]);
            smA[rr * SP + c] = v;
            if (c > 0) smB[rr * SP + c - 1] = v;
        }
    }
    // Halo: cols 64..69, 70 rows x 6 cols = 420 elems.
#pragma unroll
    for (int k = 0; k < 4; k++) {
        const int idx = tid + k * TPB;                 // 0..511
        if (idx < SM_H * 6) {
            const int rr = idx / 6;
            const int c  = 64 + (idx - rr * 6);        // 64..69
            const int gr = min(row0 + rr, H - 1);
            const int gc = min(col0 + c, W - 1);
            const float v = __ldg(&x[gr * W + gc]);
            smA[rr * SP + c] = v;
            smB[rr * SP + c - 1] = v;                  // 63..68
        }
    }
    __syncthreads();

    // ---- Compute: 2 cols x 16 rows per thread, f32x2 throughout ----
    const int tx    = tid & 31;
    const int rbase = (tid >> 5) * RPT;                // 0,16,32,48
    const int cb    = tx * 2;                          // 0..62

    u64 acc[RPT];
#pragma unroll
    for (int o = 0; o < RPT; o++) acc[o] = 0ULL;

    const float* baseA = &smA[rbase * SP + cb];
    const float* baseB = &smB[rbase * SP + cb];

#pragma unroll
    for (int kc = 0; kc < KW; kc++) {
        const float* p = (kc & 1) ? (baseB + (kc - 1)) : (baseA + kc);

        u64 w2[KH];
#pragma unroll
        for (int kr = 0; kr < KH; kr++) w2[kr] = splat2(wsm[kr * KW + kc]);

        u64 v[VLEN];
#pragma unroll
        for (int t = 0; t < VLEN; t++)
            v[t] = *(const u64*)(p + t * SP);          // aligned LDS.64

#pragma unroll
        for (int kr = 0; kr < KH; kr++)
#pragma unroll
            for (int o = 0; o < RPT; o++)
                acc[o] = fma2(v[kr + o], w2[kr], acc[o]);
    }

    // ---- Epilogue: bias add + STG.64 (OW even: pairs never straddle) ----
    const u64 b2 = splat2(__ldg(&bias[0]));
    const int ocol = col0 + cb;
    if (ocol < OW) {
#pragma unroll
        for (int o = 0; o < RPT; o++) {
            const int orow = row0 + rbase + o;
            if (orow < OH) {
                u64 r;
                asm("add.rn.f32x2 %0, %1, %2;" : "=l"(r) : "l"(acc[o]), "l"(b2));
                *(u64*)&out[(size_t)orow * OW + ocol] = r;
            }
        }
    }
}

extern "C" void kernel_launch(void* const* d_in, const int* in_sizes, int n_in,
                              void* d_out, int out_size)
{
    const float* x    = (const float*)d_in[0];
    const float* wgt  = (const float*)d_in[1];
    const float* bias = (const float*)d_in[2];
    float* out        = (float*)d_out;

    dim3 block(TPB, 1, 1);
    dim3 grid((OW + TILE_X - 1) / TILE_X, (OH + TILE_Y - 1) / TILE_Y, 1);
    conv7x7_r16_kernel<<<grid, block>>>(x, wgt, bias, out);
}